// round 12
// baseline (speedup 1.0000x reference)
#include <cuda_runtime.h>
#include <cstdint>

#define B_SZ   16384
#define IN_D   4096
#define T_SZ   6
#define H_SZ   256
#define TH     (T_SZ * H_SZ)   // 1536

// ---------------------------------------------------------------------------
// Scratch (device globals per allocation-guard rules)
// ---------------------------------------------------------------------------
__device__ float g_h1[(size_t)B_SZ * TH];    // relu(x @ W1^T + b1)        ~100.7 MB
__device__ float g_h2[(size_t)B_SZ * TH];    // relu(h1 @ W2_t^T + b2)     ~100.7 MB
__device__ float g_R [(size_t)B_SZ * T_SZ * 8]; // per (b,t): 6 logits + vmean
__device__ float g_prep[1824];               // Wq[6*256], wv[256], cq[6], cv

// ---------------------------------------------------------------------------
// tf32 mma helpers
// ---------------------------------------------------------------------------
__device__ __forceinline__ unsigned f2tf32(float x) {
    unsigned r;
    asm("cvt.rna.tf32.f32 %0, %1;" : "=r"(r) : "f"(x));
    return r;
}

__device__ __forceinline__ void mma_tf32(float* d, const unsigned* a, const unsigned* b) {
    asm volatile(
        "mma.sync.aligned.m16n8k8.row.col.f32.tf32.tf32.f32 "
        "{%0,%1,%2,%3}, {%4,%5,%6,%7}, {%8,%9}, {%0,%1,%2,%3};\n"
        : "+f"(d[0]), "+f"(d[1]), "+f"(d[2]), "+f"(d[3])
        : "r"(a[0]), "r"(a[1]), "r"(a[2]), "r"(a[3]), "r"(b[0]), "r"(b[1]));
}

// ---------------------------------------------------------------------------
// GEMM: C[m,n] = relu( sum_k A[m,k]*B[n,k] + bias[n] )   (NT, K-major both)
// Tiles: 128x128x32, 256 threads (8 warps, 2x4), warp tile 64x32, 3-stage cp.async
// blockIdx.z selects a "task" slice via the *Zoff offsets (block-diagonal GEMM2).
// All dims are exact multiples of the tiles -> no bounds checks.
// ---------------------------------------------------------------------------
#define BM 128
#define BN 128
#define BK 32
#define SM_LDA 36                   // BK + 4 pad -> conflict-free frag loads
#define TILE_FLOATS  (BM * SM_LDA)  // 4608
#define STAGE_FLOATS (2 * TILE_FLOATS)
#define GEMM_SMEM_BYTES (3 * STAGE_FLOATS * 4)   // 110592

__global__ void __launch_bounds__(256, 1) gemm_relu_tf32(
    const float* __restrict__ A, int lda, int aZoff,
    const float* __restrict__ Bm, int ldb, int bZoff,
    const float* __restrict__ bias, int biasZoff,
    float* __restrict__ C, int ldc, int cZoff,
    int KT)
{
    extern __shared__ float sm[];
    const int tid  = threadIdx.x;
    const int lane = tid & 31;
    const int warp = tid >> 5;
    const int wm   = warp & 1;   // 2 warps over M
    const int wn   = warp >> 1;  // 4 warps over N
    const int z    = blockIdx.z;

    const float* gA = A  + (size_t)blockIdx.y * BM * lda + (size_t)z * aZoff;
    const float* gB = Bm + (size_t)blockIdx.x * BN * ldb + (size_t)z * bZoff;
    const float* gbias = bias + (size_t)z * biasZoff + blockIdx.x * BN;
    float* gC = C + (size_t)blockIdx.y * BM * ldc + (size_t)z * cZoff + blockIdx.x * BN;

    float acc[4][4][4];
#pragma unroll
    for (int i = 0; i < 4; i++)
#pragma unroll
        for (int j = 0; j < 4; j++)
#pragma unroll
            for (int k = 0; k < 4; k++) acc[i][j][k] = 0.f;

    auto load_stage = [&](int stage, int kt) {
        float* sA = sm + stage * STAGE_FLOATS;
        float* sB = sA + TILE_FLOATS;
        const float* gAk = gA + kt * BK;
        const float* gBk = gB + kt * BK;
#pragma unroll
        for (int i = 0; i < 4; i++) {
            int f  = tid + i * 256;     // 1024 float4s per tile
            int r  = f >> 3;
            int c4 = f & 7;
            unsigned da = (unsigned)__cvta_generic_to_shared(sA + r * SM_LDA + c4 * 4);
            asm volatile("cp.async.cg.shared.global [%0], [%1], 16;\n"
                         :: "r"(da), "l"(gAk + (size_t)r * lda + c4 * 4));
            unsigned db = (unsigned)__cvta_generic_to_shared(sB + r * SM_LDA + c4 * 4);
            asm volatile("cp.async.cg.shared.global [%0], [%1], 16;\n"
                         :: "r"(db), "l"(gBk + (size_t)r * ldb + c4 * 4));
        }
        asm volatile("cp.async.commit_group;\n");
    };

    load_stage(0, 0);
    load_stage(1, 1);   // KT >= 2 always

    for (int kt = 0; kt < KT; ++kt) {
        if (kt + 1 < KT) asm volatile("cp.async.wait_group 1;\n" ::: "memory");
        else             asm volatile("cp.async.wait_group 0;\n" ::: "memory");
        __syncthreads();
        if (kt + 2 < KT) load_stage((kt + 2) % 3, kt + 2);

        const float* sA = sm + (kt % 3) * STAGE_FLOATS;
        const float* sB = sA + TILE_FLOATS;
#pragma unroll
        for (int ks = 0; ks < 4; ks++) {
            unsigned af[4][4], bf[4][2];
            const int kc = ks * 8 + (lane & 3);
#pragma unroll
            for (int mt = 0; mt < 4; mt++) {
                int r = wm * 64 + mt * 16 + (lane >> 2);
                af[mt][0] = f2tf32(sA[r * SM_LDA + kc]);
                af[mt][1] = f2tf32(sA[(r + 8) * SM_LDA + kc]);
                af[mt][2] = f2tf32(sA[r * SM_LDA + kc + 4]);
                af[mt][3] = f2tf32(sA[(r + 8) * SM_LDA + kc + 4]);
            }
#pragma unroll
            for (int nt = 0; nt < 4; nt++) {
                int n = wn * 32 + nt * 8 + (lane >> 2);
                bf[nt][0] = f2tf32(sB[n * SM_LDA + kc]);
                bf[nt][1] = f2tf32(sB[n * SM_LDA + kc + 4]);
            }
#pragma unroll
            for (int mt = 0; mt < 4; mt++)
#pragma unroll
                for (int nt = 0; nt < 4; nt++)
                    mma_tf32(acc[mt][nt], af[mt], bf[nt]);
        }
        // no trailing sync needed: top-of-loop sync orders compute(kt-1) before load into its buffer
    }

    // Epilogue: + bias, relu, store (c0/c1 adjacent -> float2)
#pragma unroll
    for (int mt = 0; mt < 4; mt++) {
        int r0 = wm * 64 + mt * 16 + (lane >> 2);
#pragma unroll
        for (int nt = 0; nt < 4; nt++) {
            int c0 = wn * 32 + nt * 8 + 2 * (lane & 3);
            float b0 = gbias[c0], b1 = gbias[c0 + 1];
            float2 v01 = make_float2(fmaxf(acc[mt][nt][0] + b0, 0.f),
                                     fmaxf(acc[mt][nt][1] + b1, 0.f));
            float2 v23 = make_float2(fmaxf(acc[mt][nt][2] + b0, 0.f),
                                     fmaxf(acc[mt][nt][3] + b1, 0.f));
            *(float2*)(gC + (size_t)r0 * ldc + c0)       = v01;
            *(float2*)(gC + (size_t)(r0 + 8) * ldc + c0) = v23;
        }
    }
}

// ---------------------------------------------------------------------------
// Prep: Wq = tq @ keyW (6x256), cq = tq @ keyb, wv = mean_o valW[o,:], cv = mean(valb)
// ---------------------------------------------------------------------------
__global__ void prep_kernel(const float* __restrict__ tq, const float* __restrict__ keyW,
                            const float* __restrict__ keyb, const float* __restrict__ valW,
                            const float* __restrict__ valb)
{
    int h = threadIdx.x;  // 0..255
    float a0 = 0, a1 = 0, a2 = 0, a3 = 0, a4 = 0, a5 = 0, wv = 0;
    for (int o = 0; o < 256; o++) {
        float kw = keyW[o * 256 + h];
        a0 += tq[0 * 256 + o] * kw;
        a1 += tq[1 * 256 + o] * kw;
        a2 += tq[2 * 256 + o] * kw;
        a3 += tq[3 * 256 + o] * kw;
        a4 += tq[4 * 256 + o] * kw;
        a5 += tq[5 * 256 + o] * kw;
        wv += valW[o * 256 + h];
    }
    g_prep[0 * 256 + h] = a0;
    g_prep[1 * 256 + h] = a1;
    g_prep[2 * 256 + h] = a2;
    g_prep[3 * 256 + h] = a3;
    g_prep[4 * 256 + h] = a4;
    g_prep[5 * 256 + h] = a5;
    g_prep[1536 + h] = wv * (1.0f / 256.0f);
    if (h < 6) {
        float c = 0;
        for (int o = 0; o < 256; o++) c += tq[h * 256 + o] * keyb[o];
        g_prep[1792 + h] = c;
    }
    if (h == 6) {
        float c = 0;
        for (int o = 0; o < 256; o++) c += valb[o];
        g_prep[1798] = c * (1.0f / 256.0f);
    }
}

// ---------------------------------------------------------------------------
// Reduce: per row r = b*6+t of h2 (256 floats), 7 dots: 6 logits + vmean.
// One warp per row, 8 rows per block.
// ---------------------------------------------------------------------------
__global__ void __launch_bounds__(256) reduce_kernel()
{
    __shared__ float sp[1800];
    for (int i = threadIdx.x; i < 1800; i += 256) sp[i] = g_prep[i];
    __syncthreads();

    const int warp = threadIdx.x >> 5, lane = threadIdx.x & 31;
    const int r = blockIdx.x * 8 + warp;           // 0 .. B*T-1
    const float* hrow = g_h2 + (size_t)r * 256;

    float va[8];
    *(float4*)(va)     = *(const float4*)(hrow + lane * 4);
    *(float4*)(va + 4) = *(const float4*)(hrow + 128 + lane * 4);

    float s[7] = {0, 0, 0, 0, 0, 0, 0};
#pragma unroll
    for (int j = 0; j < 8; j++) {
        int h = (j < 4) ? (lane * 4 + j) : (128 + lane * 4 + (j - 4));
        float hv = va[j];
#pragma unroll
        for (int q = 0; q < 6; q++) s[q] += hv * sp[q * 256 + h];
        s[6] += hv * sp[1536 + h];
    }
#pragma unroll
    for (int t = 0; t < 7; t++) {
        float v = s[t];
        v += __shfl_xor_sync(0xffffffffu, v, 16);
        v += __shfl_xor_sync(0xffffffffu, v, 8);
        v += __shfl_xor_sync(0xffffffffu, v, 4);
        v += __shfl_xor_sync(0xffffffffu, v, 2);
        v += __shfl_xor_sync(0xffffffffu, v, 1);
        s[t] = v;
    }
    if (lane == 0) {
        float* out = g_R + (size_t)r * 8;
#pragma unroll
        for (int q = 0; q < 6; q++) out[q] = (s[q] + sp[1792 + q]) * 0.0625f; // /sqrt(256)
        out[6] = s[6] + sp[1798];
    }
}

// ---------------------------------------------------------------------------
// Final: per b, 6x6 softmax(I + 0.1*logits/m) @ vmean, sigmoid, clip.
// ---------------------------------------------------------------------------
__global__ void final_kernel(float* __restrict__ out, const float* __restrict__ biasPtr)
{
    int b = blockIdx.x * 256 + threadIdx.x;
    float lg[6][6], vm[6];
#pragma unroll
    for (int k = 0; k < 6; k++) {
        const float* rk = g_R + ((size_t)b * 6 + k) * 8;
#pragma unroll
        for (int q = 0; q < 6; q++) lg[q][k] = rk[q];
        vm[k] = rk[6];
    }
    float bv = *biasPtr;
#pragma unroll
    for (int q = 0; q < 6; q++) {
        float m = lg[q][0];
#pragma unroll
        for (int k = 1; k < 6; k++) m = fmaxf(m, lg[q][k]);
        m += 1e-8f;
        float s[6];
        float mx = -1e30f;
#pragma unroll
        for (int k = 0; k < 6; k++) {
            s[k] = ((k == q) ? 1.0f : 0.0f) + 0.1f * (lg[q][k] / m);
            mx = fmaxf(mx, s[k]);
        }
        float den = 0.f, num = 0.f;
#pragma unroll
        for (int k = 0; k < 6; k++) {
            float e = expf(s[k] - mx);
            den += e;
            num += e * vm[k];
        }
        float y = num / den - bv;
        float p = 1.0f / (1.0f + expf(-y));
        p = fminf(fmaxf(p, 1e-7f), 1.0f - 1e-7f);
        out[(size_t)b * 6 + q] = p;
    }
}

// ---------------------------------------------------------------------------
// Launch
// ---------------------------------------------------------------------------
extern "C" void kernel_launch(void* const* d_in, const int* in_sizes, int n_in,
                              void* d_out, int out_size)
{
    const float* x    = (const float*)d_in[0];
    const float* W1   = (const float*)d_in[1];   // [T*H, IN] = [1536, 4096]
    const float* b1   = (const float*)d_in[2];   // [1536]
    const float* W2   = (const float*)d_in[3];   // [T, H, H]
    const float* b2   = (const float*)d_in[4];   // [T, H]
    const float* tq   = (const float*)d_in[5];   // [6, 256]
    const float* keyW = (const float*)d_in[6];   // [256, 256]
    const float* keyb = (const float*)d_in[7];
    const float* valW = (const float*)d_in[8];
    const float* valb = (const float*)d_in[9];
    const float* bias = (const float*)d_in[10];  // scalar
    float* out = (float*)d_out;

    float *h1p = nullptr, *h2p = nullptr;
    cudaGetSymbolAddress((void**)&h1p, g_h1);
    cudaGetSymbolAddress((void**)&h2p, g_h2);

    cudaFuncSetAttribute(gemm_relu_tf32,
                         cudaFuncAttributeMaxDynamicSharedMemorySize, GEMM_SMEM_BYTES);

    prep_kernel<<<1, 256>>>(tq, keyW, keyb, valW, valb);

    // GEMM1: h1 = relu(x @ W1^T + b1); M=16384, N=1536, K=4096
    gemm_relu_tf32<<<dim3(12, 128, 1), 256, GEMM_SMEM_BYTES>>>(
        x, IN_D, 0,
        W1, IN_D, 0,
        b1, 0,
        h1p, TH, 0,
        IN_D / BK);

    // GEMM2 (block-diagonal over tasks): h2[:, t] = relu(h1[:, t] @ W2_t^T + b2_t)
    gemm_relu_tf32<<<dim3(2, 128, T_SZ), 256, GEMM_SMEM_BYTES>>>(
        h1p, TH, H_SZ,
        W2, H_SZ, H_SZ * H_SZ,
        b2, H_SZ,
        h2p, TH, H_SZ,
        H_SZ / BK);

    reduce_kernel<<<(B_SZ * T_SZ) / 8, 256>>>();
    final_kernel<<<B_SZ / 256, 256>>>(out, bias);
}

// round 15
// speedup vs baseline: 2.2638x; 2.2638x over previous
#include <cuda_runtime.h>
#include <cuda_bf16.h>
#include <cstdint>

#define B_SZ 16384
#define IN_D 4096
#define T_SZ 6
#define H_SZ 256
#define TH   1536

// ---------------------------------------------------------------------------
// Scratch (device globals per allocation-guard rules)
// ---------------------------------------------------------------------------
__device__ __nv_bfloat16 g_xb [(size_t)B_SZ * IN_D];           // 128 MB
__device__ __nv_bfloat16 g_w1b[(size_t)TH * IN_D];             // 12.6 MB
__device__ __nv_bfloat16 g_w2b[(size_t)T_SZ * H_SZ * H_SZ];    // 0.75 MB
__device__ __nv_bfloat16 g_h1b[(size_t)B_SZ * TH];             // 50.3 MB
__device__ float g_h2[(size_t)B_SZ * TH];                      // 100.7 MB
__device__ float g_R[(size_t)B_SZ * T_SZ * 8];                 // 3 MB
__device__ float g_prep[1824];

// ---------------------------------------------------------------------------
// mma / ldmatrix helpers (legacy path — PTX baseline, compiles for sm_103)
// ---------------------------------------------------------------------------
__device__ __forceinline__ void mma_bf16(float* d, const uint32_t* a, const uint32_t* b) {
    asm volatile(
        "mma.sync.aligned.m16n8k16.row.col.f32.bf16.bf16.f32 "
        "{%0,%1,%2,%3}, {%4,%5,%6,%7}, {%8,%9}, {%0,%1,%2,%3};\n"
        : "+f"(d[0]), "+f"(d[1]), "+f"(d[2]), "+f"(d[3])
        : "r"(a[0]), "r"(a[1]), "r"(a[2]), "r"(a[3]), "r"(b[0]), "r"(b[1]));
}
__device__ __forceinline__ void ldsm4(uint32_t* r, uint32_t addr) {
    asm volatile("ldmatrix.sync.aligned.m8n8.x4.shared.b16 {%0,%1,%2,%3}, [%4];"
                 : "=r"(r[0]), "=r"(r[1]), "=r"(r[2]), "=r"(r[3]) : "r"(addr));
}

// ---------------------------------------------------------------------------
// GEMM: C[m,n] = relu( sum_k A[m,k]*B[n,k] + bias[n] ), bf16 operands K-major.
// CTA tile 128x128, BK=64 (128B rows, SW128 swizzle), 4-stage cp.async,
// 8 warps (2 over M x 4 over N), warp tile 64x32, ldmatrix fragment loads.
// MODE 0: store bf16 (GEMM1 -> h1).  MODE 1: store fp32 (GEMM2 -> h2).
// blockIdx.z + *Zoff give block-diagonal GEMM2. All dims exact multiples.
// ---------------------------------------------------------------------------
#define BM 128
#define BN 128
#define BKB 64
#define A_BYTES (BM*128)                  // 16384
#define STG_BYTES (2*A_BYTES)             // 32768 (A then B)
#define NSTAGE 4
#define SMEM_DYN (NSTAGE*STG_BYTES + 1024)

template<int MODE>
__global__ void __launch_bounds__(256, 1) gemm_bf16(
    const __nv_bfloat16* __restrict__ A, int lda, int aZoff,
    const __nv_bfloat16* __restrict__ Bw, int ldb, int bZoff,
    const float* __restrict__ bias, int biasZoff,
    void* __restrict__ Cout, int ldc, int cZoff,
    int KT)
{
    extern __shared__ char smraw[];
    uint32_t sm0  = (uint32_t)__cvta_generic_to_shared(smraw);
    uint32_t base = (sm0 + 1023u) & ~1023u;

    const int tid  = threadIdx.x;
    const int lane = tid & 31;
    const int warp = tid >> 5;
    const int wm   = warp & 1;
    const int wn   = warp >> 1;
    const int z    = blockIdx.z;

    const char* gA = (const char*)(A  + (size_t)blockIdx.y * BM * lda + (size_t)z * aZoff);
    const char* gB = (const char*)(Bw + (size_t)blockIdx.x * BN * ldb + (size_t)z * bZoff);
    const float* gbias = bias + (size_t)z * biasZoff + blockIdx.x * BN;

    const size_t ldab = (size_t)lda * 2;
    const size_t ldbb = (size_t)ldb * 2;

    float acc[4][4][4];
#pragma unroll
    for (int i = 0; i < 4; i++)
#pragma unroll
        for (int j = 0; j < 4; j++)
#pragma unroll
            for (int k = 0; k < 4; k++) acc[i][j][k] = 0.f;

    // per-thread cp.async pattern: f = tid + i*256 over 1024 16B chunks/tile
    auto load_stage = [&](int stage, int kt) {
        uint32_t sA = base + stage * STG_BYTES;
        uint32_t sB = sA + A_BYTES;
        const char* gAk = gA + (size_t)kt * 128;   // 64 bf16 = 128 B per k-block
        const char* gBk = gB + (size_t)kt * 128;
#pragma unroll
        for (int i = 0; i < 4; i++) {
            int f  = tid + i * 256;
            int r  = f >> 3;
            int c8 = f & 7;
            uint32_t off = (uint32_t)(r * 128 + ((c8 ^ (r & 7)) << 4));
            asm volatile("cp.async.cg.shared.global [%0], [%1], 16;\n"
                         :: "r"(sA + off), "l"(gAk + (size_t)r * ldab + c8 * 16));
            asm volatile("cp.async.cg.shared.global [%0], [%1], 16;\n"
                         :: "r"(sB + off), "l"(gBk + (size_t)r * ldbb + c8 * 16));
        }
        asm volatile("cp.async.commit_group;\n");
    };

    load_stage(0, 0);
    load_stage(1, 1);
    load_stage(2, 2);    // KT >= 4 always (4 or 64)

    // ldmatrix source rows/cols (swizzle uses row&7, invariant across +16 row steps)
    const int arow = wm * 64 + (lane & 15);
    const int brow = wn * 32 + ((lane >> 4) << 3) + (lane & 7);

    for (int kt = 0; kt < KT; ++kt) {
        if (KT - kt >= 3)      asm volatile("cp.async.wait_group 2;\n" ::: "memory");
        else if (KT - kt == 2) asm volatile("cp.async.wait_group 1;\n" ::: "memory");
        else                   asm volatile("cp.async.wait_group 0;\n" ::: "memory");
        __syncthreads();
        if (kt + 3 < KT) load_stage((kt + 3) & (NSTAGE - 1), kt + 3);

        uint32_t sA = base + (kt & (NSTAGE - 1)) * STG_BYTES;
        uint32_t sB = sA + A_BYTES;
#pragma unroll
        for (int ks = 0; ks < 4; ks++) {
            uint32_t af[4][4], bf[2][4];
            const int ac8 = ks * 2 + (lane >> 4);
            const int bc8 = ks * 2 + ((lane >> 3) & 1);
#pragma unroll
            for (int mt = 0; mt < 4; mt++) {
                uint32_t ad = sA + (uint32_t)((arow + mt * 16) * 128 + ((ac8 ^ (arow & 7)) << 4));
                ldsm4(af[mt], ad);
            }
#pragma unroll
            for (int p = 0; p < 2; p++) {
                uint32_t bd = sB + (uint32_t)((brow + p * 16) * 128 + ((bc8 ^ (brow & 7)) << 4));
                ldsm4(bf[p], bd);
            }
#pragma unroll
            for (int mt = 0; mt < 4; mt++)
#pragma unroll
                for (int nt = 0; nt < 4; nt++)
                    mma_bf16(acc[mt][nt], af[mt], &bf[nt >> 1][(nt & 1) * 2]);
        }
    }

    // Epilogue: + bias, relu; c0/c1 adjacent cols
#pragma unroll
    for (int mt = 0; mt < 4; mt++) {
        int r0 = wm * 64 + mt * 16 + (lane >> 2);
#pragma unroll
        for (int nt = 0; nt < 4; nt++) {
            int c0 = wn * 32 + nt * 8 + 2 * (lane & 3);
            float b0 = gbias[c0], b1 = gbias[c0 + 1];
            float f0 = fmaxf(acc[mt][nt][0] + b0, 0.f);
            float f1 = fmaxf(acc[mt][nt][1] + b1, 0.f);
            float f2 = fmaxf(acc[mt][nt][2] + b0, 0.f);
            float f3 = fmaxf(acc[mt][nt][3] + b1, 0.f);
            if (MODE == 0) {
                __nv_bfloat16* crow = (__nv_bfloat16*)Cout
                    + ((size_t)blockIdx.y * BM) * ldc + (size_t)z * cZoff
                    + (size_t)blockIdx.x * BN;
                __nv_bfloat162 p01 = __floats2bfloat162_rn(f0, f1);
                __nv_bfloat162 p23 = __floats2bfloat162_rn(f2, f3);
                *(uint32_t*)(crow + (size_t)r0 * ldc + c0)       = *(uint32_t*)&p01;
                *(uint32_t*)(crow + (size_t)(r0 + 8) * ldc + c0) = *(uint32_t*)&p23;
            } else {
                float* crow = (float*)Cout
                    + ((size_t)blockIdx.y * BM) * ldc + (size_t)z * cZoff
                    + (size_t)blockIdx.x * BN;
                *(float2*)(crow + (size_t)r0 * ldc + c0)       = make_float2(f0, f1);
                *(float2*)(crow + (size_t)(r0 + 8) * ldc + c0) = make_float2(f2, f3);
            }
        }
    }
}

// ---------------------------------------------------------------------------
// fp32 -> bf16 convert (vectorized, grid-stride)
// ---------------------------------------------------------------------------
__global__ void convert_kernel(const float4* __restrict__ src, uint2* __restrict__ dst, int n4)
{
    int i = blockIdx.x * blockDim.x + threadIdx.x;
    const int stride = gridDim.x * blockDim.x;
    for (; i < n4; i += stride) {
        float4 v = src[i];
        __nv_bfloat162 a = __floats2bfloat162_rn(v.x, v.y);
        __nv_bfloat162 b = __floats2bfloat162_rn(v.z, v.w);
        uint2 o;
        o.x = *(uint32_t*)&a;
        o.y = *(uint32_t*)&b;
        dst[i] = o;
    }
}

// ---------------------------------------------------------------------------
// Prep: Wq = tq @ keyW, cq = tq @ keyb, wv = mean_o valW[o,:], cv = mean(valb)
// ---------------------------------------------------------------------------
__global__ void prep_kernel(const float* __restrict__ tq, const float* __restrict__ keyW,
                            const float* __restrict__ keyb, const float* __restrict__ valW,
                            const float* __restrict__ valb)
{
    int h = threadIdx.x;
    float a0 = 0, a1 = 0, a2 = 0, a3 = 0, a4 = 0, a5 = 0, wv = 0;
    for (int o = 0; o < 256; o++) {
        float kw = keyW[o * 256 + h];
        a0 += tq[0 * 256 + o] * kw;
        a1 += tq[1 * 256 + o] * kw;
        a2 += tq[2 * 256 + o] * kw;
        a3 += tq[3 * 256 + o] * kw;
        a4 += tq[4 * 256 + o] * kw;
        a5 += tq[5 * 256 + o] * kw;
        wv += valW[o * 256 + h];
    }
    g_prep[0 * 256 + h] = a0;
    g_prep[1 * 256 + h] = a1;
    g_prep[2 * 256 + h] = a2;
    g_prep[3 * 256 + h] = a3;
    g_prep[4 * 256 + h] = a4;
    g_prep[5 * 256 + h] = a5;
    g_prep[1536 + h] = wv * (1.0f / 256.0f);
    if (h < 6) {
        float c = 0;
        for (int o = 0; o < 256; o++) c += tq[h * 256 + o] * keyb[o];
        g_prep[1792 + h] = c;
    }
    if (h == 6) {
        float c = 0;
        for (int o = 0; o < 256; o++) c += valb[o];
        g_prep[1798] = c * (1.0f / 256.0f);
    }
}

// ---------------------------------------------------------------------------
// Reduce: per row r = b*6+t of h2 (256 floats), 7 dots: 6 logits + vmean.
// ---------------------------------------------------------------------------
__global__ void __launch_bounds__(256) reduce_kernel()
{
    __shared__ float sp[1800];
    for (int i = threadIdx.x; i < 1800; i += 256) sp[i] = g_prep[i];
    __syncthreads();

    const int warp = threadIdx.x >> 5, lane = threadIdx.x & 31;
    const int r = blockIdx.x * 8 + warp;
    const float* hrow = g_h2 + (size_t)r * 256;

    float va[8];
    *(float4*)(va)     = *(const float4*)(hrow + lane * 4);
    *(float4*)(va + 4) = *(const float4*)(hrow + 128 + lane * 4);

    float s[7] = {0, 0, 0, 0, 0, 0, 0};
#pragma unroll
    for (int j = 0; j < 8; j++) {
        int h = (j < 4) ? (lane * 4 + j) : (128 + lane * 4 + (j - 4));
        float hv = va[j];
#pragma unroll
        for (int q = 0; q < 6; q++) s[q] += hv * sp[q * 256 + h];
        s[6] += hv * sp[1536 + h];
    }
#pragma unroll
    for (int t = 0; t < 7; t++) {
        float v = s[t];
        v += __shfl_xor_sync(0xffffffffu, v, 16);
        v += __shfl_xor_sync(0xffffffffu, v, 8);
        v += __shfl_xor_sync(0xffffffffu, v, 4);
        v += __shfl_xor_sync(0xffffffffu, v, 2);
        v += __shfl_xor_sync(0xffffffffu, v, 1);
        s[t] = v;
    }
    if (lane == 0) {
        float* out = g_R + (size_t)r * 8;
#pragma unroll
        for (int q = 0; q < 6; q++) out[q] = (s[q] + sp[1792 + q]) * 0.0625f; // /sqrt(256)
        out[6] = s[6] + sp[1798];
    }
}

// ---------------------------------------------------------------------------
// Final: per b, 6x6 softmax(I + 0.1*logits/m) @ vmean, sigmoid, clip.
// ---------------------------------------------------------------------------
__global__ void final_kernel(float* __restrict__ out, const float* __restrict__ biasPtr)
{
    int b = blockIdx.x * 256 + threadIdx.x;
    float lg[6][6], vm[6];
#pragma unroll
    for (int k = 0; k < 6; k++) {
        const float* rk = g_R + ((size_t)b * 6 + k) * 8;
#pragma unroll
        for (int q = 0; q < 6; q++) lg[q][k] = rk[q];
        vm[k] = rk[6];
    }
    float bv = *biasPtr;
#pragma unroll
    for (int q = 0; q < 6; q++) {
        float m = lg[q][0];
#pragma unroll
        for (int k = 1; k < 6; k++) m = fmaxf(m, lg[q][k]);
        m += 1e-8f;
        float s[6];
        float mx = -1e30f;
#pragma unroll
        for (int k = 0; k < 6; k++) {
            s[k] = ((k == q) ? 1.0f : 0.0f) + 0.1f * (lg[q][k] / m);
            mx = fmaxf(mx, s[k]);
        }
        float den = 0.f, num = 0.f;
#pragma unroll
        for (int k = 0; k < 6; k++) {
            float e = expf(s[k] - mx);
            den += e;
            num += e * vm[k];
        }
        float y = num / den - bv;
        float p = 1.0f / (1.0f + expf(-y));
        p = fminf(fmaxf(p, 1e-7f), 1.0f - 1e-7f);
        out[(size_t)b * 6 + q] = p;
    }
}

// ---------------------------------------------------------------------------
// Launch
// ---------------------------------------------------------------------------
extern "C" void kernel_launch(void* const* d_in, const int* in_sizes, int n_in,
                              void* d_out, int out_size)
{
    const float* x    = (const float*)d_in[0];
    const float* W1   = (const float*)d_in[1];   // [1536, 4096]
    const float* b1   = (const float*)d_in[2];
    const float* W2   = (const float*)d_in[3];   // [6, 256, 256]
    const float* b2   = (const float*)d_in[4];
    const float* tq   = (const float*)d_in[5];
    const float* keyW = (const float*)d_in[6];
    const float* keyb = (const float*)d_in[7];
    const float* valW = (const float*)d_in[8];
    const float* valb = (const float*)d_in[9];
    const float* bias = (const float*)d_in[10];
    float* out = (float*)d_out;

    __nv_bfloat16 *xb = nullptr, *w1b = nullptr, *w2b = nullptr, *h1b = nullptr;
    float* h2p = nullptr;
    cudaGetSymbolAddress((void**)&xb,  g_xb);
    cudaGetSymbolAddress((void**)&w1b, g_w1b);
    cudaGetSymbolAddress((void**)&w2b, g_w2b);
    cudaGetSymbolAddress((void**)&h1b, g_h1b);
    cudaGetSymbolAddress((void**)&h2p, g_h2);

    cudaFuncSetAttribute(gemm_bf16<0>, cudaFuncAttributeMaxDynamicSharedMemorySize, SMEM_DYN);
    cudaFuncSetAttribute(gemm_bf16<1>, cudaFuncAttributeMaxDynamicSharedMemorySize, SMEM_DYN);

    convert_kernel<<<4096, 256>>>((const float4*)x,  (uint2*)xb,  B_SZ * IN_D / 4);
    convert_kernel<<<1024, 256>>>((const float4*)W1, (uint2*)w1b, TH * IN_D / 4);
    convert_kernel<<<96,   256>>>((const float4*)W2, (uint2*)w2b, T_SZ * H_SZ * H_SZ / 4);
    prep_kernel<<<1, 256>>>(tq, keyW, keyb, valW, valb);

    // GEMM1: h1 = relu(x @ W1^T + b1); M=16384, N=1536, K=4096 -> bf16
    gemm_bf16<0><<<dim3(12, 128, 1), 256, SMEM_DYN>>>(
        xb, IN_D, 0,
        w1b, IN_D, 0,
        b1, 0,
        (void*)h1b, TH, 0,
        IN_D / BKB);

    // GEMM2 (block-diagonal): h2[:,t] = relu(h1[:,t] @ W2_t^T + b2_t) -> fp32
    gemm_bf16<1><<<dim3(2, 128, T_SZ), 256, SMEM_DYN>>>(
        h1b, TH, H_SZ,
        w2b, H_SZ, H_SZ * H_SZ,
        b2, H_SZ,
        (void*)h2p, TH, H_SZ,
        H_SZ / BKB);

    reduce_kernel<<<(B_SZ * T_SZ) / 8, 256>>>();
    final_kernel<<<B_SZ / 256, 256>>>(out, bias);
}

// round 16
// speedup vs baseline: 2.5984x; 1.1478x over previous
#include <cuda_runtime.h>
#include <cuda_bf16.h>
#include <cstdint>

#define B_SZ 16384
#define IN_D 4096
#define T_SZ 6
#define H_SZ 256
#define TH   1536

// ---------------------------------------------------------------------------
// Scratch (device globals per allocation-guard rules)
// ---------------------------------------------------------------------------
__device__ __nv_bfloat16 g_xb [(size_t)B_SZ * IN_D];           // 128 MB
__device__ __nv_bfloat16 g_w1b[(size_t)TH * IN_D];             // 12.6 MB
__device__ __nv_bfloat16 g_w2b[(size_t)T_SZ * H_SZ * H_SZ];    // 0.75 MB
__device__ __nv_bfloat16 g_h1b[(size_t)B_SZ * TH];             // 50.3 MB
__device__ float g_R[(size_t)B_SZ * T_SZ * 8];                 // 3 MB
__device__ float g_prep[1824];

// ---------------------------------------------------------------------------
// mma / ldmatrix helpers (legacy path — PTX baseline, compiles for sm_103)
// ---------------------------------------------------------------------------
__device__ __forceinline__ void mma_bf16(float* d, const uint32_t* a, const uint32_t* b) {
    asm volatile(
        "mma.sync.aligned.m16n8k16.row.col.f32.bf16.bf16.f32 "
        "{%0,%1,%2,%3}, {%4,%5,%6,%7}, {%8,%9}, {%0,%1,%2,%3};\n"
        : "+f"(d[0]), "+f"(d[1]), "+f"(d[2]), "+f"(d[3])
        : "r"(a[0]), "r"(a[1]), "r"(a[2]), "r"(a[3]), "r"(b[0]), "r"(b[1]));
}
__device__ __forceinline__ void ldsm4(uint32_t* r, uint32_t addr) {
    asm volatile("ldmatrix.sync.aligned.m8n8.x4.shared.b16 {%0,%1,%2,%3}, [%4];"
                 : "=r"(r[0]), "=r"(r[1]), "=r"(r[2]), "=r"(r[3]) : "r"(addr));
}
__device__ __forceinline__ void cpasync16(uint32_t dst, const void* src) {
    asm volatile("cp.async.cg.shared.global [%0], [%1], 16;\n" :: "r"(dst), "l"(src));
}

// ===========================================================================
// GEMM1: h1 = relu(x @ W1^T + b1) -> bf16.  M=16384, N=1536, K=4096.
// CTA 256x128, BK=64 (128B rows, SW128 swizzle), 4-stage cp.async,
// 8 warps: 4 over M x 2 over N, warp tile 64x64, ldmatrix fragments.
// ===========================================================================
#define STG_BYTES 49152                  // A(32KB or 16KB) + B — same for both GEMMs
#define NSTAGE 4
#define G1_SMEM (NSTAGE*STG_BYTES + 1024)            // 197632
#define G2_SMEM (NSTAGE*STG_BYTES + 2080*4 + 1024)   // 205952

__global__ void __launch_bounds__(256, 1) gemm1_kernel(
    const __nv_bfloat16* __restrict__ A, const __nv_bfloat16* __restrict__ Bw,
    const float* __restrict__ bias, __nv_bfloat16* __restrict__ C)
{
    extern __shared__ char smraw[];
    uint32_t sm0  = (uint32_t)__cvta_generic_to_shared(smraw);
    uint32_t base = (sm0 + 1023u) & ~1023u;

    const int tid  = threadIdx.x;
    const int lane = tid & 31;
    const int warp = tid >> 5;
    const int wm   = warp & 3;   // 4 warps over M (64 each)
    const int wn   = warp >> 2;  // 2 warps over N (64 each)

    const char* gA = (const char*)(A  + (size_t)blockIdx.y * 256 * IN_D);
    const char* gB = (const char*)(Bw + (size_t)blockIdx.x * 128 * IN_D);
    const float* gbias = bias + blockIdx.x * 128;

    float acc[4][8][4];
#pragma unroll
    for (int i = 0; i < 4; i++)
#pragma unroll
        for (int j = 0; j < 8; j++)
#pragma unroll
            for (int k = 0; k < 4; k++) acc[i][j][k] = 0.f;

    auto load_stage = [&](int stage, int kt) {
        uint32_t sA = base + stage * STG_BYTES;        // A: 256 rows * 128B = 32KB
        uint32_t sB = sA + 32768;                      // B: 128 rows * 128B = 16KB
        const char* gAk = gA + (size_t)kt * 128;
        const char* gBk = gB + (size_t)kt * 128;
#pragma unroll
        for (int i = 0; i < 8; i++) {                  // 2048 A chunks
            int f = tid + i * 256, r = f >> 3, c8 = f & 7;
            uint32_t off = (uint32_t)(r * 128 + ((c8 ^ (r & 7)) << 4));
            cpasync16(sA + off, gAk + (size_t)r * (IN_D * 2) + c8 * 16);
        }
#pragma unroll
        for (int i = 0; i < 4; i++) {                  // 1024 B chunks
            int f = tid + i * 256, r = f >> 3, c8 = f & 7;
            uint32_t off = (uint32_t)(r * 128 + ((c8 ^ (r & 7)) << 4));
            cpasync16(sB + off, gBk + (size_t)r * (IN_D * 2) + c8 * 16);
        }
        asm volatile("cp.async.commit_group;\n");
    };

    load_stage(0, 0);
    load_stage(1, 1);
    load_stage(2, 2);

    const int arow = wm * 64 + (lane & 15);
    const int brow = wn * 64 + ((lane >> 4) << 3) + (lane & 7);
    const int KT = IN_D / 64;   // 64

    for (int kt = 0; kt < KT; ++kt) {
        if (KT - kt >= 3)      asm volatile("cp.async.wait_group 2;\n" ::: "memory");
        else if (KT - kt == 2) asm volatile("cp.async.wait_group 1;\n" ::: "memory");
        else                   asm volatile("cp.async.wait_group 0;\n" ::: "memory");
        __syncthreads();
        if (kt + 3 < KT) load_stage((kt + 3) & (NSTAGE - 1), kt + 3);

        uint32_t sA = base + (kt & (NSTAGE - 1)) * STG_BYTES;
        uint32_t sB = sA + 32768;
#pragma unroll
        for (int ks = 0; ks < 4; ks++) {
            uint32_t af[4][4], bf[4][4];
            const int ac8 = ks * 2 + (lane >> 4);
            const int bc8 = ks * 2 + ((lane >> 3) & 1);
#pragma unroll
            for (int mt = 0; mt < 4; mt++)
                ldsm4(af[mt], sA + (uint32_t)((arow + mt * 16) * 128 + ((ac8 ^ (arow & 7)) << 4)));
#pragma unroll
            for (int nb = 0; nb < 4; nb++)
                ldsm4(bf[nb], sB + (uint32_t)((brow + nb * 16) * 128 + ((bc8 ^ (brow & 7)) << 4)));
#pragma unroll
            for (int mt = 0; mt < 4; mt++)
#pragma unroll
                for (int nt = 0; nt < 8; nt++)
                    mma_bf16(acc[mt][nt], af[mt], &bf[nt >> 1][(nt & 1) * 2]);
        }
    }

    // Epilogue: + bias, relu, bf16 store
    __nv_bfloat16* crow = C + ((size_t)blockIdx.y * 256) * TH + (size_t)blockIdx.x * 128;
#pragma unroll
    for (int mt = 0; mt < 4; mt++) {
        int r0 = wm * 64 + mt * 16 + (lane >> 2);
#pragma unroll
        for (int nt = 0; nt < 8; nt++) {
            int c0 = wn * 64 + nt * 8 + 2 * (lane & 3);
            float b0 = gbias[c0], b1 = gbias[c0 + 1];
            __nv_bfloat162 p01 = __floats2bfloat162_rn(fmaxf(acc[mt][nt][0] + b0, 0.f),
                                                       fmaxf(acc[mt][nt][1] + b1, 0.f));
            __nv_bfloat162 p23 = __floats2bfloat162_rn(fmaxf(acc[mt][nt][2] + b0, 0.f),
                                                       fmaxf(acc[mt][nt][3] + b1, 0.f));
            *(uint32_t*)(crow + (size_t)r0 * TH + c0)       = *(uint32_t*)&p01;
            *(uint32_t*)(crow + (size_t)(r0 + 8) * TH + c0) = *(uint32_t*)&p23;
        }
    }
}

// ===========================================================================
// GEMM2 + fused reduce: per task z, h2 = relu(h1[:,z] @ W2_z^T + b2_z),
// then per-row 7 dots (6 logits + vmean) -> g_R.  CTA 128x256, K=256.
// 8 warps: 2 over M x 4 over N, warp tile 64x64. Epilogue parks h2 tile in
// the (dead) stage smem with row stride 257 and does the dots from there.
// ===========================================================================
#define HS_STRIDE 257

__global__ void __launch_bounds__(256, 1) gemm2_fused_kernel(
    const __nv_bfloat16* __restrict__ A, const __nv_bfloat16* __restrict__ Bw,
    const float* __restrict__ b2, float* __restrict__ R)
{
    extern __shared__ char smraw[];
    uint32_t sm0  = (uint32_t)__cvta_generic_to_shared(smraw);
    uint32_t base = (sm0 + 1023u) & ~1023u;
    char*  smal = smraw + (base - sm0);
    float* hsf  = (float*)smal;                         // epilogue h2 tile (reuses stages)
    float* auxf = (float*)(smal + NSTAGE * STG_BYTES);  // prep[1800] + bias[256]

    const int tid  = threadIdx.x;
    const int lane = tid & 31;
    const int warp = tid >> 5;
    const int wm   = warp & 1;   // 2 warps over M (64 each)
    const int wn   = warp >> 1;  // 4 warps over N (64 each)
    const int z    = blockIdx.z;

    const char* gA = (const char*)(A  + (size_t)blockIdx.y * 128 * TH + (size_t)z * 256);
    const char* gB = (const char*)(Bw + (size_t)z * 65536);

    for (int i = tid; i < 1800; i += 256) auxf[i] = g_prep[i];
    for (int i = tid; i < 256;  i += 256) auxf[1800 + i] = b2[z * 256 + i];

    float acc[4][8][4];
#pragma unroll
    for (int i = 0; i < 4; i++)
#pragma unroll
        for (int j = 0; j < 8; j++)
#pragma unroll
            for (int k = 0; k < 4; k++) acc[i][j][k] = 0.f;

    auto load_stage = [&](int stage, int kt) {
        uint32_t sA = base + stage * STG_BYTES;        // A: 128 rows * 128B = 16KB
        uint32_t sB = sA + 16384;                      // B: 256 rows * 128B = 32KB
        const char* gAk = gA + (size_t)kt * 128;
        const char* gBk = gB + (size_t)kt * 128;
#pragma unroll
        for (int i = 0; i < 4; i++) {                  // 1024 A chunks
            int f = tid + i * 256, r = f >> 3, c8 = f & 7;
            uint32_t off = (uint32_t)(r * 128 + ((c8 ^ (r & 7)) << 4));
            cpasync16(sA + off, gAk + (size_t)r * (TH * 2) + c8 * 16);
        }
#pragma unroll
        for (int i = 0; i < 8; i++) {                  // 2048 B chunks
            int f = tid + i * 256, r = f >> 3, c8 = f & 7;
            uint32_t off = (uint32_t)(r * 128 + ((c8 ^ (r & 7)) << 4));
            cpasync16(sB + off, gBk + (size_t)r * (H_SZ * 2) + c8 * 16);
        }
        asm volatile("cp.async.commit_group;\n");
    };

    load_stage(0, 0);
    load_stage(1, 1);
    load_stage(2, 2);

    const int arow = wm * 64 + (lane & 15);
    const int brow = wn * 64 + ((lane >> 4) << 3) + (lane & 7);
    const int KT = H_SZ / 64;   // 4

    for (int kt = 0; kt < KT; ++kt) {
        if (KT - kt >= 3)      asm volatile("cp.async.wait_group 2;\n" ::: "memory");
        else if (KT - kt == 2) asm volatile("cp.async.wait_group 1;\n" ::: "memory");
        else                   asm volatile("cp.async.wait_group 0;\n" ::: "memory");
        __syncthreads();
        if (kt + 3 < KT) load_stage((kt + 3) & (NSTAGE - 1), kt + 3);

        uint32_t sA = base + (kt & (NSTAGE - 1)) * STG_BYTES;
        uint32_t sB = sA + 16384;
#pragma unroll
        for (int ks = 0; ks < 4; ks++) {
            uint32_t af[4][4], bf[4][4];
            const int ac8 = ks * 2 + (lane >> 4);
            const int bc8 = ks * 2 + ((lane >> 3) & 1);
#pragma unroll
            for (int mt = 0; mt < 4; mt++)
                ldsm4(af[mt], sA + (uint32_t)((arow + mt * 16) * 128 + ((ac8 ^ (arow & 7)) << 4)));
#pragma unroll
            for (int nb = 0; nb < 4; nb++)
                ldsm4(bf[nb], sB + (uint32_t)((brow + nb * 16) * 128 + ((bc8 ^ (brow & 7)) << 4)));
#pragma unroll
            for (int mt = 0; mt < 4; mt++)
#pragma unroll
                for (int nt = 0; nt < 8; nt++)
                    mma_bf16(acc[mt][nt], af[mt], &bf[nt >> 1][(nt & 1) * 2]);
        }
    }
    __syncthreads();   // all warps done reading stages; safe to overwrite with hs

    // relu(acc + bias) -> smem tile (row stride 257 floats: conflict-free column walk)
#pragma unroll
    for (int mt = 0; mt < 4; mt++) {
        int r0 = wm * 64 + mt * 16 + (lane >> 2);
#pragma unroll
        for (int nt = 0; nt < 8; nt++) {
            int c0 = wn * 64 + nt * 8 + 2 * (lane & 3);
            float b0 = auxf[1800 + c0], b1 = auxf[1800 + c0 + 1];
            hsf[r0 * HS_STRIDE + c0]           = fmaxf(acc[mt][nt][0] + b0, 0.f);
            hsf[r0 * HS_STRIDE + c0 + 1]       = fmaxf(acc[mt][nt][1] + b1, 0.f);
            hsf[(r0 + 8) * HS_STRIDE + c0]     = fmaxf(acc[mt][nt][2] + b0, 0.f);
            hsf[(r0 + 8) * HS_STRIDE + c0 + 1] = fmaxf(acc[mt][nt][3] + b1, 0.f);
        }
    }
    __syncthreads();

    // 7 dots per row; 2 threads per row (128 h each), combine via shfl
    const int row = tid >> 1;
    const int h0  = (tid & 1) * 128;
    float s[7] = {0, 0, 0, 0, 0, 0, 0};
#pragma unroll 4
    for (int h = 0; h < 128; h++) {
        const int hh = h0 + h;
        float v = hsf[row * HS_STRIDE + hh];
#pragma unroll
        for (int q = 0; q < 6; q++) s[q] += v * auxf[q * 256 + hh];
        s[6] += v * auxf[1536 + hh];
    }
#pragma unroll
    for (int t = 0; t < 7; t++) s[t] += __shfl_xor_sync(0xffffffffu, s[t], 1);
    if ((tid & 1) == 0) {
        const size_t m = (size_t)blockIdx.y * 128 + row;
        float* o = R + (m * T_SZ + z) * 8;
#pragma unroll
        for (int q = 0; q < 6; q++) o[q] = (s[q] + auxf[1792 + q]) * 0.0625f; // /sqrt(256)
        o[6] = s[6] + auxf[1798];
    }
}

// ---------------------------------------------------------------------------
// fp32 -> bf16 convert (vectorized, grid-stride)
// ---------------------------------------------------------------------------
__global__ void convert_kernel(const float4* __restrict__ src, uint2* __restrict__ dst, int n4)
{
    int i = blockIdx.x * blockDim.x + threadIdx.x;
    const int stride = gridDim.x * blockDim.x;
    for (; i < n4; i += stride) {
        float4 v = src[i];
        __nv_bfloat162 a = __floats2bfloat162_rn(v.x, v.y);
        __nv_bfloat162 b = __floats2bfloat162_rn(v.z, v.w);
        uint2 o;
        o.x = *(uint32_t*)&a;
        o.y = *(uint32_t*)&b;
        dst[i] = o;
    }
}

// ---------------------------------------------------------------------------
// Prep (parallel, 7 blocks): blocks 0-5: Wq[q,:] = tq[q,:] @ keyW, cq[q];
// block 6: wv = mean_o valW[o,:], cv = mean(valb).
// ---------------------------------------------------------------------------
__global__ void __launch_bounds__(256) prep_kernel(
    const float* __restrict__ tq, const float* __restrict__ keyW,
    const float* __restrict__ keyb, const float* __restrict__ valW,
    const float* __restrict__ valb)
{
    __shared__ float tqs[256];
    __shared__ float red[256];
    const int q = blockIdx.x;
    const int h = threadIdx.x;

    if (q < 6) {
        tqs[h] = tq[q * 256 + h];
        red[h] = tqs[h] * keyb[h];
        __syncthreads();
        float a = 0.f;
#pragma unroll 16
        for (int o = 0; o < 256; o++) a += tqs[o] * keyW[o * 256 + h];
        g_prep[q * 256 + h] = a;
        for (int sft = 128; sft > 0; sft >>= 1) {
            if (h < sft) red[h] += red[h + sft];
            __syncthreads();
        }
        if (h == 0) g_prep[1792 + q] = red[0];
    } else {
        red[h] = valb[h];
        __syncthreads();
        float a = 0.f;
#pragma unroll 16
        for (int o = 0; o < 256; o++) a += valW[o * 256 + h];
        g_prep[1536 + h] = a * (1.0f / 256.0f);
        for (int sft = 128; sft > 0; sft >>= 1) {
            if (h < sft) red[h] += red[h + sft];
            __syncthreads();
        }
        if (h == 0) g_prep[1798] = red[0] * (1.0f / 256.0f);
    }
}

// ---------------------------------------------------------------------------
// Final: per b, 6x6 softmax(I + 0.1*logits/m) @ vmean, sigmoid, clip.
// ---------------------------------------------------------------------------
__global__ void final_kernel(float* __restrict__ out, const float* __restrict__ biasPtr)
{
    int b = blockIdx.x * 256 + threadIdx.x;
    float lg[6][6], vm[6];
#pragma unroll
    for (int k = 0; k < 6; k++) {
        const float* rk = g_R + ((size_t)b * 6 + k) * 8;
#pragma unroll
        for (int q = 0; q < 6; q++) lg[q][k] = rk[q];
        vm[k] = rk[6];
    }
    float bv = *biasPtr;
#pragma unroll
    for (int q = 0; q < 6; q++) {
        float m = lg[q][0];
#pragma unroll
        for (int k = 1; k < 6; k++) m = fmaxf(m, lg[q][k]);
        m += 1e-8f;
        float s[6];
        float mx = -1e30f;
#pragma unroll
        for (int k = 0; k < 6; k++) {
            s[k] = ((k == q) ? 1.0f : 0.0f) + 0.1f * (lg[q][k] / m);
            mx = fmaxf(mx, s[k]);
        }
        float den = 0.f, num = 0.f;
#pragma unroll
        for (int k = 0; k < 6; k++) {
            float e = expf(s[k] - mx);
            den += e;
            num += e * vm[k];
        }
        float y = num / den - bv;
        float p = 1.0f / (1.0f + expf(-y));
        p = fminf(fmaxf(p, 1e-7f), 1.0f - 1e-7f);
        out[(size_t)b * 6 + q] = p;
    }
}

// ---------------------------------------------------------------------------
// Launch
// ---------------------------------------------------------------------------
extern "C" void kernel_launch(void* const* d_in, const int* in_sizes, int n_in,
                              void* d_out, int out_size)
{
    const float* x    = (const float*)d_in[0];
    const float* W1   = (const float*)d_in[1];   // [1536, 4096]
    const float* b1   = (const float*)d_in[2];
    const float* W2   = (const float*)d_in[3];   // [6, 256, 256]
    const float* b2   = (const float*)d_in[4];
    const float* tq   = (const float*)d_in[5];
    const float* keyW = (const float*)d_in[6];
    const float* keyb = (const float*)d_in[7];
    const float* valW = (const float*)d_in[8];
    const float* valb = (const float*)d_in[9];
    const float* bias = (const float*)d_in[10];
    float* out = (float*)d_out;

    __nv_bfloat16 *xb = nullptr, *w1b = nullptr, *w2b = nullptr, *h1b = nullptr;
    float* Rp = nullptr;
    cudaGetSymbolAddress((void**)&xb,  g_xb);
    cudaGetSymbolAddress((void**)&w1b, g_w1b);
    cudaGetSymbolAddress((void**)&w2b, g_w2b);
    cudaGetSymbolAddress((void**)&h1b, g_h1b);
    cudaGetSymbolAddress((void**)&Rp,  g_R);

    cudaFuncSetAttribute(gemm1_kernel, cudaFuncAttributeMaxDynamicSharedMemorySize, G1_SMEM);
    cudaFuncSetAttribute(gemm2_fused_kernel, cudaFuncAttributeMaxDynamicSharedMemorySize, G2_SMEM);

    convert_kernel<<<4096, 256>>>((const float4*)x,  (uint2*)xb,  B_SZ * IN_D / 4);
    convert_kernel<<<1024, 256>>>((const float4*)W1, (uint2*)w1b, TH * IN_D / 4);
    convert_kernel<<<96,   256>>>((const float4*)W2, (uint2*)w2b, T_SZ * H_SZ * H_SZ / 4);
    prep_kernel<<<7, 256>>>(tq, keyW, keyb, valW, valb);

    // GEMM1: M=16384 (64 tiles of 256), N=1536 (12 tiles of 128), K=4096
    gemm1_kernel<<<dim3(12, 64, 1), 256, G1_SMEM>>>(xb, w1b, b1, h1b);

    // GEMM2 + fused reduce: per task z, tiles of 128 rows x full 256 cols
    gemm2_fused_kernel<<<dim3(1, 128, T_SZ), 256, G2_SMEM>>>(h1b, w2b, b2, Rp);

    final_kernel<<<B_SZ / 256, 256>>>(out, bias);
}